// round 10
// baseline (speedup 1.0000x reference)
#include <cuda_runtime.h>

#define NN 4096      // nodes
#define NE 4096      // hyperedges
#define NF 128       // features
#define CAP 192      // per-list capacity (max degree ~58 expected)

// ---------------- scratch (static __device__, zero-initialized) ----------
__device__ float g_theta[NN * NF];        // X @ W            (2 MB, L2-resident)
__device__ float g_U[NE * NF];            // De^-1 H^T theta  (2 MB)
__device__ float g_inv_dv[NN];
__device__ float g_inv_de[NE];
__device__ int   g_col_cnt[NE];           // MUST be 0 at k_fused entry (zero at load;
__device__ int   g_row_cnt[NN];           //  spmm1/spmm2 re-zero after reading)
__device__ int   g_col_idx[NE * CAP];
__device__ int   g_row_idx[NN * CAP];

// ---------------- K1: fused init + theta + CSR/CSC build -----------------
// blockIdx roles:  [0, 1024)             -> build: 4 H rows per CTA (64 KB stream)
//                  [1024, 1024+128)      -> theta tile
//                  [1024+128, 1024+144)  -> diag inverses
#define BUILD_CTAS 1024
__global__ void __launch_bounds__(256, 2) k_fused(const float* __restrict__ X,
                                                  const float* __restrict__ W,
                                                  const float* __restrict__ H,
                                                  const float* __restrict__ Dv,
                                                  const float* __restrict__ De) {
    __shared__ float Xs[32][NF];          // theta branch only

    const int b   = blockIdx.x;
    const int tid = threadIdx.x;

    if (b < BUILD_CTAS) {
        // ---- build: 4 rows of H per CTA. ALL 16 LDG.128 front-batched
        // (64 dedicated dest registers; launch_bounds(256,2) gives ptxas
        //  a 128-reg budget so it cannot split the batch). H is 0.0/1.0,
        //  so nonzero test is integer (x|y|z|w)!=0 on the raw bits.
        const int4* __restrict__ row4 =
            reinterpret_cast<const int4*>(H) + (size_t)b * 4096;

        int4 v[16];
        #pragma unroll
        for (int j = 0; j < 16; j++)
            v[j] = row4[tid + j * 256];

        #pragma unroll
        for (int j = 0; j < 16; j++) {
            if ((v[j].x | v[j].y | v[j].z | v[j].w) != 0) {   // ~3% taken
                int off   = tid + j * 256;        // float4 index within chunk
                int n     = b * 4 + (off >> 10);
                int ebase = (off << 2) & (NE - 1);
                int comp[4] = {v[j].x, v[j].y, v[j].z, v[j].w};
                #pragma unroll
                for (int c = 0; c < 4; c++) {
                    if (comp[c] != 0) {
                        int e = ebase + c;
                        int p = atomicAdd(&g_row_cnt[n], 1);   // 4096 addrs
                        if (p < CAP) g_row_idx[(size_t)n * CAP + p] = e;
                        int q = atomicAdd(&g_col_cnt[e], 1);   // 4096 addrs
                        if (q < CAP) g_col_idx[(size_t)e * CAP + q] = n;
                    }
                }
            }
        }

    } else if (b < BUILD_CTAS + 128) {
        // ---- theta = X @ W : 32-row x 128-col tile --------------------
        const int row0 = (b - BUILD_CTAS) * 32;
        #pragma unroll
        for (int i = tid; i < 32 * NF; i += 256)
            Xs[i >> 7][i & 127] = X[(size_t)row0 * NF + i];
        __syncthreads();

        const int fp = tid & 63;          // float2 column
        const int rg = tid >> 6;          // row group 0..3
        const float2* __restrict__ W2 = reinterpret_cast<const float2*>(W);

        float acc[8][2];
        #pragma unroll
        for (int i = 0; i < 8; i++) { acc[i][0] = 0.f; acc[i][1] = 0.f; }

        #pragma unroll 4
        for (int k = 0; k < NF; k++) {
            float2 w = __ldg(&W2[k * 64 + fp]);
            #pragma unroll
            for (int i = 0; i < 8; i++) {
                float x = Xs[rg * 8 + i][k];
                acc[i][0] += x * w.x;
                acc[i][1] += x * w.y;
            }
        }
        #pragma unroll
        for (int i = 0; i < 8; i++) {
            int r = row0 + rg * 8 + i;
            *reinterpret_cast<float2*>(&g_theta[(size_t)r * NF + fp * 2]) =
                make_float2(acc[i][0], acc[i][1]);
        }

    } else {
        // ---- diagonal inverses ----------------------------------------
        int i = (b - BUILD_CTAS - 128) * 256 + tid;
        if (i < NN) {
            g_inv_dv[i] = 1.0f / Dv[(size_t)i * (NN + 1)];
            g_inv_de[i] = 1.0f / De[(size_t)i * (NE + 1)];
        }
    }
}

// ---------------- SpMM gather core: warp per output row, float4 ----------
__device__ __forceinline__ float4 gather_row(const int* __restrict__ idx,
                                             int cnt,
                                             const float4* __restrict__ src,
                                             int lane) {
    float4 acc = make_float4(0.f, 0.f, 0.f, 0.f);
    int i = 0;
    for (; i + 8 <= cnt; i += 8) {
        int id[8];
        #pragma unroll
        for (int j = 0; j < 8; j++) id[j] = idx[i + j];
        float4 v[8];
        #pragma unroll
        for (int j = 0; j < 8; j++) v[j] = src[(size_t)id[j] * 32 + lane];
        #pragma unroll
        for (int j = 0; j < 8; j++) {
            acc.x += v[j].x; acc.y += v[j].y; acc.z += v[j].z; acc.w += v[j].w;
        }
    }
    for (; i < cnt; i++) {
        float4 v = src[(size_t)idx[i] * 32 + lane];
        acc.x += v.x; acc.y += v.y; acc.z += v.z; acc.w += v.w;
    }
    return acc;
}

// ---------------- K2: U[e] = inv_de[e] * sum_{n in col[e]} theta[n] ------
__global__ void __launch_bounds__(128) k_spmm1() {
    const int e    = blockIdx.x * 4 + (threadIdx.x >> 5);
    const int lane = threadIdx.x & 31;

    int cnt = g_col_cnt[e];
    if (cnt > CAP) cnt = CAP;
    float4 acc = gather_row(g_col_idx + (size_t)e * CAP, cnt,
                            reinterpret_cast<const float4*>(g_theta), lane);

    float s = g_inv_de[e];
    acc.x *= s; acc.y *= s; acc.z *= s; acc.w *= s;
    reinterpret_cast<float4*>(g_U)[(size_t)e * 32 + lane] = acc;

    if (lane == 0) g_col_cnt[e] = 0;      // leave zeroed for next launch
}

// ---------------- K3: Y[n] = inv_dv[n] * sum_{e in row[n]} U[e] ----------
__global__ void __launch_bounds__(128) k_spmm2(float* __restrict__ out) {
    const int n    = blockIdx.x * 4 + (threadIdx.x >> 5);
    const int lane = threadIdx.x & 31;

    int cnt = g_row_cnt[n];
    if (cnt > CAP) cnt = CAP;
    float4 acc = gather_row(g_row_idx + (size_t)n * CAP, cnt,
                            reinterpret_cast<const float4*>(g_U), lane);

    float s = g_inv_dv[n];
    acc.x *= s; acc.y *= s; acc.z *= s; acc.w *= s;
    reinterpret_cast<float4*>(out)[(size_t)n * 32 + lane] = acc;

    if (lane == 0) g_row_cnt[n] = 0;      // leave zeroed for next launch
}

// ---------------- launch --------------------------------------------------
extern "C" void kernel_launch(void* const* d_in, const int* in_sizes, int n_in,
                              void* d_out, int out_size) {
    const float* X  = (const float*)d_in[0];   // [4096,128]
    const float* H  = (const float*)d_in[1];   // [4096,4096]
    const float* Dv = (const float*)d_in[2];   // [4096,4096] diag
    const float* De = (const float*)d_in[3];   // [4096,4096] diag
    const float* W  = (const float*)d_in[4];   // [128,128]
    float* out = (float*)d_out;                // [4096,128]

    k_fused<<<BUILD_CTAS + 128 + 16, 256>>>(X, W, H, Dv, De);
    k_spmm1<<<NE / 4, 128>>>();
    k_spmm2<<<NN / 4, 128>>>(out);
}

// round 11
// speedup vs baseline: 1.2401x; 1.2401x over previous
#include <cuda_runtime.h>
#include <cstdint>

#define NN 4096      // nodes
#define NE 4096      // hyperedges
#define NF 128       // features
#define CAP 192      // per-list capacity (max degree ~58 expected)

// ---------------- scratch (static __device__, zero-initialized) ----------
__device__ float g_theta[NN * NF];        // X @ W            (2 MB, L2-resident)
__device__ float g_U[NE * NF];            // De^-1 H^T theta  (2 MB)
__device__ float g_inv_dv[NN];
__device__ float g_inv_de[NE];
__device__ int   g_col_cnt[NE];           // MUST be 0 at k_fused entry (zero at load;
                                          //  k_spmm1 re-zeroes after reading)
__device__ int   g_row_cnt[NN];           // plain-stored by k_fused each launch
__device__ int   g_col_idx[NE * CAP];
__device__ int   g_row_idx[NN * CAP];

// ---------------- cp.async helpers ---------------------------------------
__device__ __forceinline__ void cp_async16(uint32_t saddr, const void* gaddr) {
    asm volatile("cp.async.cg.shared.global [%0], [%1], 16;\n"
                 :: "r"(saddr), "l"(gaddr) : "memory");
}
__device__ __forceinline__ void cp_commit() {
    asm volatile("cp.async.commit_group;\n" ::: "memory");
}
template <int N>
__device__ __forceinline__ void cp_wait() {
    asm volatile("cp.async.wait_group %0;\n" :: "n"(N) : "memory");
}

// ---------------- K1: fused init + theta + CSR/CSC build -----------------
// blockIdx roles:  [0, 1024)             -> build: 4 H rows via cp.async pipeline
//                  [1024, 1024+128)      -> theta tile
//                  [1024+128, 1024+144)  -> diag inverses
#define BUILD_CTAS 1024
__global__ void __launch_bounds__(256) k_fused(const float* __restrict__ X,
                                               const float* __restrict__ W,
                                               const float* __restrict__ H,
                                               const float* __restrict__ Dv,
                                               const float* __restrict__ De) {
    __shared__ __align__(16) int4 s_stage[2][1024];   // 2 x 16 KB double buffer
    __shared__ int s_cnt;

    const int b   = blockIdx.x;
    const int tid = threadIdx.x;

    if (b < BUILD_CTAS) {
        // ---- build: 4 rows of H, double-buffered cp.async (register-free MLP)
        const char* __restrict__ hbase =
            reinterpret_cast<const char*>(H) + (size_t)b * 4 * 16384;

        // prefetch stage 0
        {
            uint32_t sb = (uint32_t)__cvta_generic_to_shared(&s_stage[0][0]);
            #pragma unroll
            for (int k = 0; k < 4; k++)
                cp_async16(sb + (uint32_t)(tid + k * 256) * 16,
                           hbase + (size_t)(tid + k * 256) * 16);
            cp_commit();
        }

        #pragma unroll
        for (int s = 0; s < 4; s++) {
            if (s < 3) {                       // prefetch next stage
                uint32_t sb = (uint32_t)__cvta_generic_to_shared(&s_stage[(s + 1) & 1][0]);
                const char* g = hbase + (size_t)(s + 1) * 16384;
                #pragma unroll
                for (int k = 0; k < 4; k++)
                    cp_async16(sb + (uint32_t)(tid + k * 256) * 16,
                               g + (size_t)(tid + k * 256) * 16);
                cp_commit();
                cp_wait<1>();                  // stage s landed, s+1 in flight
            } else {
                cp_wait<0>();
            }
            if (tid == 0) s_cnt = 0;
            __syncthreads();                   // smem data + s_cnt visible

            const int n = b * 4 + s;
            const int4* __restrict__ buf = s_stage[s & 1];
            #pragma unroll
            for (int k = 0; k < 4; k++) {
                int idx = tid + k * 256;       // float4 index within row
                int4 v = buf[idx];             // conflict-free LDS.128
                if ((v.x | v.y | v.z | v.w) != 0) {      // ~3% taken
                    int ebase = idx << 2;
                    int comp[4] = {v.x, v.y, v.z, v.w};
                    #pragma unroll
                    for (int c = 0; c < 4; c++) {
                        if (comp[c] != 0) {
                            int e = ebase + c;
                            int p = atomicAdd(&s_cnt, 1);          // smem
                            if (p < CAP) g_row_idx[(size_t)n * CAP + p] = e;
                            int q = atomicAdd(&g_col_cnt[e], 1);   // 4096 addrs
                            if (q < CAP) g_col_idx[(size_t)e * CAP + q] = n;
                        }
                    }
                }
            }
            __syncthreads();                   // all reads done before buffer reuse
            if (tid == 0) g_row_cnt[n] = (s_cnt < CAP) ? s_cnt : CAP;
        }

    } else if (b < BUILD_CTAS + 128) {
        // ---- theta = X @ W : 32-row x 128-col tile (reuses s_stage as Xs)
        float (*Xs)[NF] = reinterpret_cast<float (*)[NF]>(s_stage);
        const int row0 = (b - BUILD_CTAS) * 32;
        #pragma unroll
        for (int i = tid; i < 32 * NF; i += 256)
            Xs[i >> 7][i & 127] = X[(size_t)row0 * NF + i];
        __syncthreads();

        const int fp = tid & 63;          // float2 column
        const int rg = tid >> 6;          // row group 0..3
        const float2* __restrict__ W2 = reinterpret_cast<const float2*>(W);

        float acc[8][2];
        #pragma unroll
        for (int i = 0; i < 8; i++) { acc[i][0] = 0.f; acc[i][1] = 0.f; }

        #pragma unroll 4
        for (int k = 0; k < NF; k++) {
            float2 w = __ldg(&W2[k * 64 + fp]);
            #pragma unroll
            for (int i = 0; i < 8; i++) {
                float x = Xs[rg * 8 + i][k];
                acc[i][0] += x * w.x;
                acc[i][1] += x * w.y;
            }
        }
        #pragma unroll
        for (int i = 0; i < 8; i++) {
            int r = row0 + rg * 8 + i;
            *reinterpret_cast<float2*>(&g_theta[(size_t)r * NF + fp * 2]) =
                make_float2(acc[i][0], acc[i][1]);
        }

    } else {
        // ---- diagonal inverses ----------------------------------------
        int i = (b - BUILD_CTAS - 128) * 256 + tid;
        if (i < NN) {
            g_inv_dv[i] = 1.0f / Dv[(size_t)i * (NN + 1)];
            g_inv_de[i] = 1.0f / De[(size_t)i * (NE + 1)];
        }
    }
}

// ---------------- SpMM gather core: warp per output row, float4 ----------
__device__ __forceinline__ float4 gather_row(const int* __restrict__ idx,
                                             int cnt,
                                             const float4* __restrict__ src,
                                             int lane) {
    float4 acc = make_float4(0.f, 0.f, 0.f, 0.f);
    int i = 0;
    for (; i + 8 <= cnt; i += 8) {
        int id[8];
        #pragma unroll
        for (int j = 0; j < 8; j++) id[j] = idx[i + j];
        float4 v[8];
        #pragma unroll
        for (int j = 0; j < 8; j++) v[j] = src[(size_t)id[j] * 32 + lane];
        #pragma unroll
        for (int j = 0; j < 8; j++) {
            acc.x += v[j].x; acc.y += v[j].y; acc.z += v[j].z; acc.w += v[j].w;
        }
    }
    for (; i < cnt; i++) {
        float4 v = src[(size_t)idx[i] * 32 + lane];
        acc.x += v.x; acc.y += v.y; acc.z += v.z; acc.w += v.w;
    }
    return acc;
}

// ---------------- K2: U[e] = inv_de[e] * sum_{n in col[e]} theta[n] ------
__global__ void __launch_bounds__(128) k_spmm1() {
    const int e    = blockIdx.x * 4 + (threadIdx.x >> 5);
    const int lane = threadIdx.x & 31;

    int cnt = g_col_cnt[e];
    if (cnt > CAP) cnt = CAP;
    float4 acc = gather_row(g_col_idx + (size_t)e * CAP, cnt,
                            reinterpret_cast<const float4*>(g_theta), lane);

    float s = g_inv_de[e];
    acc.x *= s; acc.y *= s; acc.z *= s; acc.w *= s;
    reinterpret_cast<float4*>(g_U)[(size_t)e * 32 + lane] = acc;

    if (lane == 0) g_col_cnt[e] = 0;      // leave zeroed for next launch
}

// ---------------- K3: Y[n] = inv_dv[n] * sum_{e in row[n]} U[e] ----------
__global__ void __launch_bounds__(128) k_spmm2(float* __restrict__ out) {
    const int n    = blockIdx.x * 4 + (threadIdx.x >> 5);
    const int lane = threadIdx.x & 31;

    int cnt = g_row_cnt[n];
    if (cnt > CAP) cnt = CAP;
    float4 acc = gather_row(g_row_idx + (size_t)n * CAP, cnt,
                            reinterpret_cast<const float4*>(g_U), lane);

    float s = g_inv_dv[n];
    acc.x *= s; acc.y *= s; acc.z *= s; acc.w *= s;
    reinterpret_cast<float4*>(out)[(size_t)n * 32 + lane] = acc;
}

// ---------------- launch --------------------------------------------------
extern "C" void kernel_launch(void* const* d_in, const int* in_sizes, int n_in,
                              void* d_out, int out_size) {
    const float* X  = (const float*)d_in[0];   // [4096,128]
    const float* H  = (const float*)d_in[1];   // [4096,4096]
    const float* Dv = (const float*)d_in[2];   // [4096,4096] diag
    const float* De = (const float*)d_in[3];   // [4096,4096] diag
    const float* W  = (const float*)d_in[4];   // [128,128]
    float* out = (float*)d_out;                // [4096,128]

    k_fused<<<BUILD_CTAS + 128 + 16, 256>>>(X, W, H, Dv, De);
    k_spmm1<<<NE / 4, 128>>>();
    k_spmm2<<<NN / 4, 128>>>(out);
}